// round 14
// baseline (speedup 1.0000x reference)
#include <cuda_runtime.h>
#include <cuda_fp16.h>
#include <cstdint>
#include <math.h>

#define N_RAYS   4096
#define N_SAMP   192
#define S_TOTAL  (N_RAYS * N_SAMP)   // 786432
#define TILE_M   256
#define NT       512                  // 16 warps, 16 rows each

// ---------------------------------------------------------------------------
// helpers
// ---------------------------------------------------------------------------
__device__ __forceinline__ uint32_t smem_u32(const void* p) {
    uint32_t a;
    asm("{ .reg .u64 t; cvta.to.shared.u64 t, %1; cvt.u32.u64 %0, t; }" : "=r"(a) : "l"(p));
    return a;
}

__device__ __forceinline__ void ldsm_x4(uint32_t* r, uint32_t addr) {
    asm volatile("ldmatrix.sync.aligned.m8n8.x4.shared.b16 {%0,%1,%2,%3}, [%4];"
        : "=r"(r[0]), "=r"(r[1]), "=r"(r[2]), "=r"(r[3]) : "r"(addr));
}

__device__ __forceinline__ void mma16816(float* c, const uint32_t* a, const uint32_t* b) {
    asm volatile("mma.sync.aligned.m16n8k16.row.col.f32.f16.f16.f32 "
        "{%0,%1,%2,%3}, {%4,%5,%6,%7}, {%8,%9}, {%0,%1,%2,%3};"
        : "+f"(c[0]), "+f"(c[1]), "+f"(c[2]), "+f"(c[3])
        : "r"(a[0]), "r"(a[1]), "r"(a[2]), "r"(a[3]), "r"(b[0]), "r"(b[1]));
}

#define CP_ASYNC16(dst, src) \
    asm volatile("cp.async.cg.shared.global [%0], [%1], 16;" :: "r"(dst), "l"(src) : "memory")
#define CP_COMMIT()  asm volatile("cp.async.commit_group;" ::: "memory")
#define CP_WAIT0()   asm volatile("cp.async.wait_group 0;" ::: "memory")

// ---------------------------------------------------------------------------
// Prepared weights: fp16, B^T layout: Bt[n][k] = W[k][n], row = 256B,
// k-chunk (16B) XOR-swizzled by (n&7) for conflict-free ldmatrix.
// One contiguous buffer: W1 | W2 | W3 | WF | WR (ushort offsets below)
// ---------------------------------------------------------------------------
#define GW_W1 0
#define GW_W2 16384
#define GW_W3 32768
#define GW_WF 49152
#define GW_WR 65536
__device__ __align__(16) unsigned short g_BW[73728];

__device__ __forceinline__ uint32_t bt_off(int n, int k) {   // byte offset
    return (uint32_t)(n * 256) + (uint32_t)(((((k >> 3) ^ (n & 7))) << 4) + ((k & 7) << 1));
}

__global__ void prep_weights(const float* __restrict__ w1, const float* __restrict__ w2,
                             const float* __restrict__ w3, const float* __restrict__ wf,
                             const float* __restrict__ wr) {
    int e = blockIdx.x * blockDim.x + threadIdx.x;
    if (e < 65536) {
        int m = e >> 14, r = e & 16383;
        int k = r >> 7, n = r & 127;
        const float* W = (m == 0) ? w1 : (m == 1) ? w2 : (m == 2) ? w3 : wf;
        g_BW[m * 16384 + (bt_off(n, k) >> 1)] = __half_as_ushort(__float2half_rn(W[k * 128 + n]));
    } else if (e < 73728) {
        int r = e - 65536;
        int k = r >> 6, n = r & 63;
        g_BW[GW_WR + (bt_off(n, k) >> 1)] = __half_as_ushort(__float2half_rn(wr[k * 64 + n]));
    }
}

// ---------------------------------------------------------------------------
// smem layout
// ---------------------------------------------------------------------------
#define OFF_F      16
#define OFF_W1     16384
#define SMEM_TOTAL (16384 + 147456)    // 160 KB

// float-region indices (relative to F)
#define FB0   0
#define FB1   128
#define FB2   256
#define FB3   384
#define FBF   512
#define FBR   640
#define FW0   704     // [3][128]
#define FW2B  1088    // [3][128]
#define FWRB  1472    // [3][64]
#define FWD   1664    // [128]
#define FWO   1792    // [64][3]
#define FBD   1984
#define FBO   1985    // 3
#define FPOS  1988    // [3][256]
#define FVIEW 2756    // [3][256]

// ---------------------------------------------------------------------------
// Fused layer: act(regs 16 rows) @ Bt(smem) + bias (+3-wide concat), ReLU,
// repack to A-fragments. NP = N/16 (8 or 4). K fixed = 128 (8 k-tiles).
// ldmatrix fused with its 2 MMAs to keep live B minimal (reg cap 128).
// ---------------------------------------------------------------------------
template <int NP, bool CONCAT>
__device__ __forceinline__ void run_layer(
    const uint32_t (&A)[8][4], uint32_t (&An)[8][4],
    uint32_t wsm, const float* __restrict__ Fb,
    const float* __restrict__ Fc, const float (&pr)[2][3], int lane)
{
    const int g  = lane >> 3, ln = lane & 7;
    const int nl = ((g >> 1) << 3) + ln;   // n offset within 16-wide pair
    const int gk = g & 1;                  // k-chunk select (lo/hi 8)
    const int cb = 2 * (lane & 3);
    constexpr int NW = NP * 16;
#pragma unroll
    for (int np = 0; np < NP; np++) {
        const int n_abs = np * 16 + nl;
        const uint32_t rowb = wsm + ((uint32_t)n_abs << 8);
        const int sw = n_abs & 7;
        const int n0 = np * 16 + cb, n1 = n0 + 8;
        float ae[4], ao[4];
        {
            float be0 = Fb[n0], be1 = Fb[n0 + 1], bq0 = Fb[n1], bq1 = Fb[n1 + 1];
            if constexpr (CONCAT) {
                ae[0] = be0 + pr[0][0]*Fc[n0]   + pr[0][1]*Fc[NW+n0]   + pr[0][2]*Fc[2*NW+n0];
                ae[1] = be1 + pr[0][0]*Fc[n0+1] + pr[0][1]*Fc[NW+n0+1] + pr[0][2]*Fc[2*NW+n0+1];
                ae[2] = be0 + pr[1][0]*Fc[n0]   + pr[1][1]*Fc[NW+n0]   + pr[1][2]*Fc[2*NW+n0];
                ae[3] = be1 + pr[1][0]*Fc[n0+1] + pr[1][1]*Fc[NW+n0+1] + pr[1][2]*Fc[2*NW+n0+1];
                ao[0] = bq0 + pr[0][0]*Fc[n1]   + pr[0][1]*Fc[NW+n1]   + pr[0][2]*Fc[2*NW+n1];
                ao[1] = bq1 + pr[0][0]*Fc[n1+1] + pr[0][1]*Fc[NW+n1+1] + pr[0][2]*Fc[2*NW+n1+1];
                ao[2] = bq0 + pr[1][0]*Fc[n1]   + pr[1][1]*Fc[NW+n1]   + pr[1][2]*Fc[2*NW+n1];
                ao[3] = bq1 + pr[1][0]*Fc[n1+1] + pr[1][1]*Fc[NW+n1+1] + pr[1][2]*Fc[2*NW+n1+1];
            } else {
                ae[0] = be0; ae[1] = be1; ae[2] = be0; ae[3] = be1;
                ao[0] = bq0; ao[1] = bq1; ao[2] = bq0; ao[3] = bq1;
            }
        }
#pragma unroll
        for (int kt = 0; kt < 8; kt++) {
            uint32_t B4[4];
            ldsm_x4(B4, rowb + (uint32_t)((((kt << 1) + gk) ^ sw) << 4));
            mma16816(ae, A[kt], &B4[0]);
            mma16816(ao, A[kt], &B4[2]);
        }
        __half2 h;
        h = __floats2half2_rn(fmaxf(ae[0], 0.f), fmaxf(ae[1], 0.f)); An[np][0] = *(uint32_t*)&h;
        h = __floats2half2_rn(fmaxf(ae[2], 0.f), fmaxf(ae[3], 0.f)); An[np][1] = *(uint32_t*)&h;
        h = __floats2half2_rn(fmaxf(ao[0], 0.f), fmaxf(ao[1], 0.f)); An[np][2] = *(uint32_t*)&h;
        h = __floats2half2_rn(fmaxf(ao[2], 0.f), fmaxf(ao[3], 0.f)); An[np][3] = *(uint32_t*)&h;
    }
}

// ---------------------------------------------------------------------------
// main kernel: 16 warps x 16 rows, activations register-resident end-to-end
// ---------------------------------------------------------------------------
__global__ void __launch_bounds__(NT, 1) nerf_hmma_kernel(
    const float* __restrict__ x,
    const float* __restrict__ w0, const float* __restrict__ b0,
    const float* __restrict__ b1, const float* __restrict__ b2,
    const float* __restrict__ b3, const float* __restrict__ bd,
    const float* __restrict__ bf, const float* __restrict__ br,
    const float* __restrict__ bo, const float* __restrict__ w2,
    const float* __restrict__ wr, const float* __restrict__ wd,
    const float* __restrict__ wo, float* __restrict__ out)
{
    extern __shared__ char smem[];
    const uint32_t sb = smem_u32(smem);
    float* F = (float*)(smem + OFF_F);

    const int tid = threadIdx.x;
    const int w = tid >> 5, lane = tid & 31;
    const int q = lane >> 2;               // row-in-8 for this quad
    const int s0 = blockIdx.x * TILE_M;

    // ---- kick off async weight staging (fp16 prepped, contiguous 144KB) ----
    {
        uint64_t gw;
        asm("cvta.to.global.u64 %0, %1;" : "=l"(gw) : "l"((const void*)g_BW));
        for (int i = tid * 16; i < 147456; i += NT * 16)
            CP_ASYNC16(sb + OFF_W1 + (uint32_t)i, gw + (uint64_t)i);
        CP_COMMIT();
    }

    // ---- stage misc fp32 params + inputs ----
    for (int i = tid; i < 128; i += NT) {
        F[FB0 + i] = b0[i]; F[FB1 + i] = b1[i]; F[FB2 + i] = b2[i];
        F[FB3 + i] = b3[i]; F[FBF + i] = bf[i]; F[FWD + i] = wd[i];
    }
    if (tid < 64) F[FBR + tid] = br[tid];
    for (int i = tid; i < 384; i += NT) { F[FW0 + i] = w0[i]; F[FW2B + i] = w2[128 * 128 + i]; }
    if (tid < 192) { F[FWRB + tid] = wr[128 * 64 + tid]; F[FWO + tid] = wo[tid]; }
    if (tid == 0) { F[FBD] = bd[0]; F[FBO] = bo[0]; F[FBO + 1] = bo[1]; F[FBO + 2] = bo[2]; }
    for (int i = tid; i < TILE_M * 6; i += NT) {
        int r = i / 6, c = i % 6;
        float v = x[(size_t)(s0 + r) * 6 + c];
        if (c < 3) F[FPOS + c * 256 + r] = v; else F[FVIEW + (c - 3) * 256 + r] = v;
    }
    __syncthreads();

    uint32_t A0[8][4], A1[8][4];

    // ---- Layer 0 (K=3) via FFMA directly into A fragments ----
    {
        float px[2], py[2], pz[2];
#pragma unroll
        for (int hf = 0; hf < 2; hf++) {
            int r = w * 16 + hf * 8 + q;
            px[hf] = F[FPOS + r]; py[hf] = F[FPOS + 256 + r]; pz[hf] = F[FPOS + 512 + r];
        }
        const int cbase = 2 * (lane & 3);
#pragma unroll
        for (int kt = 0; kt < 8; kt++) {
            float Bv[4], Wx[4], Wy[4], Wz[4];
#pragma unroll
            for (int j = 0; j < 4; j++) {
                int c = kt * 16 + cbase + (j >> 1) * 8 + (j & 1);
                Bv[j] = F[FB0 + c]; Wx[j] = F[FW0 + c]; Wy[j] = F[FW0 + 128 + c]; Wz[j] = F[FW0 + 256 + c];
            }
#pragma unroll
            for (int hf = 0; hf < 2; hf++) {
                float v0 = fmaxf(Bv[0] + px[hf]*Wx[0] + py[hf]*Wy[0] + pz[hf]*Wz[0], 0.f);
                float v1 = fmaxf(Bv[1] + px[hf]*Wx[1] + py[hf]*Wy[1] + pz[hf]*Wz[1], 0.f);
                float v8 = fmaxf(Bv[2] + px[hf]*Wx[2] + py[hf]*Wy[2] + pz[hf]*Wz[2], 0.f);
                float v9 = fmaxf(Bv[3] + px[hf]*Wx[3] + py[hf]*Wy[3] + pz[hf]*Wz[3], 0.f);
                __half2 lo = __floats2half2_rn(v0, v1), hi = __floats2half2_rn(v8, v9);
                A0[kt][hf]     = *(uint32_t*)&lo;
                A0[kt][2 + hf] = *(uint32_t*)&hi;
            }
        }
    }

    // ---- weights ready? ----
    CP_WAIT0();
    __syncthreads();

    float posr[2][3], viewr[2][3];
#pragma unroll
    for (int hf = 0; hf < 2; hf++) {
        int r = w * 16 + hf * 8 + q;
        posr[hf][0] = F[FPOS + r];   posr[hf][1] = F[FPOS + 256 + r];  posr[hf][2] = F[FPOS + 512 + r];
        viewr[hf][0] = F[FVIEW + r]; viewr[hf][1] = F[FVIEW + 256 + r]; viewr[hf][2] = F[FVIEW + 512 + r];
    }

    // ---- mainloop: NO __syncthreads, activations stay in registers ----
    run_layer<8, false>(A0, A1, sb + OFF_W1,               F + FB1, F, posr, lane);          // h1
    run_layer<8, true >(A1, A0, sb + OFF_W1 + GW_W2 * 2,   F + FB2, F + FW2B, posr, lane);   // h2 (+pos)
    run_layer<8, false>(A0, A1, sb + OFF_W1 + GW_W3 * 2,   F + FB3, F, posr, lane);          // h3

    // ---- density head from h3 (A1) ----
    {
        const float bdv = F[FBD];
        const int cbase = 2 * (lane & 3);
        float d0 = 0.f, d1 = 0.f;
#pragma unroll
        for (int kt = 0; kt < 8; kt++) {
            int k0 = kt * 16 + cbase;
            float2 wlo = *(const float2*)&F[FWD + k0];
            float2 whi = *(const float2*)&F[FWD + k0 + 8];
            float2 f0 = __half22float2(*(__half2*)&A1[kt][0]);
            float2 f1 = __half22float2(*(__half2*)&A1[kt][1]);
            float2 f2 = __half22float2(*(__half2*)&A1[kt][2]);
            float2 f3 = __half22float2(*(__half2*)&A1[kt][3]);
            d0 += f0.x * wlo.x + f0.y * wlo.y + f2.x * whi.x + f2.y * whi.y;
            d1 += f1.x * wlo.x + f1.y * wlo.y + f3.x * whi.x + f3.y * whi.y;
        }
        d0 += __shfl_xor_sync(0xffffffffu, d0, 1); d0 += __shfl_xor_sync(0xffffffffu, d0, 2);
        d1 += __shfl_xor_sync(0xffffffffu, d1, 1); d1 += __shfl_xor_sync(0xffffffffu, d1, 2);
        if ((lane & 3) == 0) {
            int Ra = s0 + w * 16 + q;
            out[3 * S_TOTAL + Ra]     = fmaxf(d0 + bdv, 0.f);
            out[3 * S_TOTAL + Ra + 8] = fmaxf(d1 + bdv, 0.f);
        }
    }

    run_layer<8, false>(A1, A0, sb + OFF_W1 + GW_WF * 2,   F + FBF, F, posr, lane);          // features
    run_layer<4, true >(A0, A1, sb + OFF_W1 + GW_WR * 2,   F + FBR, F + FWRB, viewr, lane);  // r (+view)

    // ---- rgb head from r (A1, k-tiles 0..3) ----
    {
        const int cbase = 2 * (lane & 3);
        float s[2][3] = {{0.f,0.f,0.f},{0.f,0.f,0.f}};
#pragma unroll
        for (int kt = 0; kt < 4; kt++) {
            int k0 = kt * 16 + cbase, k8 = k0 + 8;
            float2 f0 = __half22float2(*(__half2*)&A1[kt][0]);
            float2 f1 = __half22float2(*(__half2*)&A1[kt][1]);
            float2 f2 = __half22float2(*(__half2*)&A1[kt][2]);
            float2 f3 = __half22float2(*(__half2*)&A1[kt][3]);
#pragma unroll
            for (int c = 0; c < 3; c++) {
                float w00 = F[FWO + k0 * 3 + c],       w01 = F[FWO + (k0 + 1) * 3 + c];
                float w08 = F[FWO + k8 * 3 + c],       w09 = F[FWO + (k8 + 1) * 3 + c];
                s[0][c] += f0.x * w00 + f0.y * w01 + f2.x * w08 + f2.y * w09;
                s[1][c] += f1.x * w00 + f1.y * w01 + f3.x * w08 + f3.y * w09;
            }
        }
#pragma unroll
        for (int hf = 0; hf < 2; hf++)
#pragma unroll
            for (int c = 0; c < 3; c++) {
                s[hf][c] += __shfl_xor_sync(0xffffffffu, s[hf][c], 1);
                s[hf][c] += __shfl_xor_sync(0xffffffffu, s[hf][c], 2);
            }
        if ((lane & 3) == 0) {
            int Ra = s0 + w * 16 + q;
#pragma unroll
            for (int hf = 0; hf < 2; hf++) {
                size_t o = (size_t)(Ra + hf * 8) * 3;
                out[o + 0] = 1.f / (1.f + expf(-(s[hf][0] + F[FBO])));
                out[o + 1] = 1.f / (1.f + expf(-(s[hf][1] + F[FBO + 1])));
                out[o + 2] = 1.f / (1.f + expf(-(s[hf][2] + F[FBO + 2])));
            }
        }
    }
}

extern "C" void kernel_launch(void* const* d_in, const int* in_sizes, int n_in,
                              void* d_out, int out_size) {
    (void)in_sizes; (void)n_in; (void)out_size;
    const float* x  = (const float*)d_in[0];
    const float* w0 = (const float*)d_in[1];  const float* b0 = (const float*)d_in[2];
    const float* w1 = (const float*)d_in[3];  const float* b1 = (const float*)d_in[4];
    const float* w2 = (const float*)d_in[5];  const float* b2 = (const float*)d_in[6];
    const float* w3 = (const float*)d_in[7];  const float* b3 = (const float*)d_in[8];
    const float* wd = (const float*)d_in[9];  const float* bd = (const float*)d_in[10];
    const float* wf = (const float*)d_in[11]; const float* bf = (const float*)d_in[12];
    const float* wr = (const float*)d_in[13]; const float* br = (const float*)d_in[14];
    const float* wo = (const float*)d_in[15]; const float* bo = (const float*)d_in[16];
    float* out = (float*)d_out;

    prep_weights<<<288, 256>>>(w1, w2, w3, wf, wr);

    cudaFuncSetAttribute(nerf_hmma_kernel,
                         cudaFuncAttributeMaxDynamicSharedMemorySize, SMEM_TOTAL);
    nerf_hmma_kernel<<<S_TOTAL / TILE_M, NT, SMEM_TOTAL>>>(
        x, w0, b0, b1, b2, b3, bd, bf, br, bo, w2, wr, wd, wo, out);
}

// round 15
// speedup vs baseline: 1.0947x; 1.0947x over previous
#include <cuda_runtime.h>
#include <cuda_fp16.h>
#include <cstdint>
#include <math.h>

#define N_RAYS   4096
#define N_SAMP   192
#define S_TOTAL  (N_RAYS * N_SAMP)   // 786432
#define TILE_M   256
#define NT       256                  // 8 warps, 32 rows each

// ---------------------------------------------------------------------------
// helpers
// ---------------------------------------------------------------------------
__device__ __forceinline__ uint32_t smem_u32(const void* p) {
    uint32_t a;
    asm("{ .reg .u64 t; cvta.to.shared.u64 t, %1; cvt.u32.u64 %0, t; }" : "=r"(a) : "l"(p));
    return a;
}

__device__ __forceinline__ void ldsm_x4(uint32_t* r, uint32_t addr) {
    asm volatile("ldmatrix.sync.aligned.m8n8.x4.shared.b16 {%0,%1,%2,%3}, [%4];"
        : "=r"(r[0]), "=r"(r[1]), "=r"(r[2]), "=r"(r[3]) : "r"(addr));
}

__device__ __forceinline__ void mma16816(float* c, const uint32_t* a, const uint32_t* b) {
    asm volatile("mma.sync.aligned.m16n8k16.row.col.f32.f16.f16.f32 "
        "{%0,%1,%2,%3}, {%4,%5,%6,%7}, {%8,%9}, {%0,%1,%2,%3};"
        : "+f"(c[0]), "+f"(c[1]), "+f"(c[2]), "+f"(c[3])
        : "r"(a[0]), "r"(a[1]), "r"(a[2]), "r"(a[3]), "r"(b[0]), "r"(b[1]));
}

#define CP_ASYNC16(dst, src) \
    asm volatile("cp.async.cg.shared.global [%0], [%1], 16;" :: "r"(dst), "l"(src) : "memory")
#define CP_COMMIT()  asm volatile("cp.async.commit_group;" ::: "memory")
#define CP_WAIT0()   asm volatile("cp.async.wait_group 0;" ::: "memory")

// ---------------------------------------------------------------------------
// Prepared weights: fp16, B^T layout: Bt[n][k] = W[k][n], row = 256B,
// k-chunk (16B) XOR-swizzled by (n&7) for conflict-free ldmatrix.
// One contiguous buffer: W1 | W2 | W3 | WF | WR (ushort offsets below)
// ---------------------------------------------------------------------------
#define GW_W1 0
#define GW_W2 16384
#define GW_W3 32768
#define GW_WF 49152
#define GW_WR 65536
__device__ __align__(16) unsigned short g_BW[73728];

__device__ __forceinline__ uint32_t bt_off(int n, int k) {   // byte offset
    return (uint32_t)(n * 256) + (uint32_t)(((((k >> 3) ^ (n & 7))) << 4) + ((k & 7) << 1));
}

__global__ void prep_weights(const float* __restrict__ w1, const float* __restrict__ w2,
                             const float* __restrict__ w3, const float* __restrict__ wf,
                             const float* __restrict__ wr) {
    int e = blockIdx.x * blockDim.x + threadIdx.x;
    if (e < 65536) {
        int m = e >> 14, r = e & 16383;
        int k = r >> 7, n = r & 127;
        const float* W = (m == 0) ? w1 : (m == 1) ? w2 : (m == 2) ? w3 : wf;
        g_BW[m * 16384 + (bt_off(n, k) >> 1)] = __half_as_ushort(__float2half_rn(W[k * 128 + n]));
    } else if (e < 73728) {
        int r = e - 65536;
        int k = r >> 6, n = r & 63;
        g_BW[GW_WR + (bt_off(n, k) >> 1)] = __half_as_ushort(__float2half_rn(wr[k * 64 + n]));
    }
}

// ---------------------------------------------------------------------------
// smem layout
// ---------------------------------------------------------------------------
#define OFF_F      16
#define OFF_W1     16384
#define SMEM_TOTAL (16384 + 147456)    // 160 KB

// float-region indices (relative to F)
#define FB0   0
#define FB1   128
#define FB2   256
#define FB3   384
#define FBF   512
#define FBR   640
#define FW0   704     // [3][128]
#define FW2B  1088    // [3][128]
#define FWRB  1472    // [3][64]
#define FWD   1664    // [128]
#define FWO   1792    // [64][3]
#define FBD   1984
#define FBO   1985    // 3
#define FPOS  1988    // [3][256]
#define FVIEW 2756    // [3][256]

// ---------------------------------------------------------------------------
// Fused layer: act(regs, 32 rows as 2 m-tiles) @ Bt(smem) + bias (+concat),
// ReLU, repack. NP = N/16. K = 128 (8 k-tiles).
// Inner loop interleaves 4 independent accumulator chains (mt0/mt1 x ae/ao)
// behind each ldmatrix -> hides HMMA RAW latency with 2 warps/SMSP.
// ---------------------------------------------------------------------------
template <int NP, bool CONCAT>
__device__ __forceinline__ void run_layer(
    const uint32_t (&A)[2][8][4], uint32_t (&An)[2][8][4],
    uint32_t wsm, const float* __restrict__ Fb,
    const float* __restrict__ Fc, const float (&pr)[2][2][3], int lane)
{
    const int g  = lane >> 3, ln = lane & 7;
    const int nl = ((g >> 1) << 3) + ln;   // n offset within 16-wide pair
    const int gk = g & 1;                  // k-chunk select (lo/hi 8)
    const int cb = 2 * (lane & 3);
    constexpr int NW = NP * 16;
#pragma unroll
    for (int np = 0; np < NP; np++) {
        const int n_abs = np * 16 + nl;
        const uint32_t rowb = wsm + ((uint32_t)n_abs << 8);
        const int sw = n_abs & 7;
        const int n0 = np * 16 + cb, n1 = n0 + 8;
        float ae[2][4], ao[2][4];
        {
            float be0 = Fb[n0], be1 = Fb[n0 + 1], bq0 = Fb[n1], bq1 = Fb[n1 + 1];
#pragma unroll
            for (int mt = 0; mt < 2; mt++) {
                if constexpr (CONCAT) {
                    ae[mt][0] = be0 + pr[mt][0][0]*Fc[n0]   + pr[mt][0][1]*Fc[NW+n0]   + pr[mt][0][2]*Fc[2*NW+n0];
                    ae[mt][1] = be1 + pr[mt][0][0]*Fc[n0+1] + pr[mt][0][1]*Fc[NW+n0+1] + pr[mt][0][2]*Fc[2*NW+n0+1];
                    ae[mt][2] = be0 + pr[mt][1][0]*Fc[n0]   + pr[mt][1][1]*Fc[NW+n0]   + pr[mt][1][2]*Fc[2*NW+n0];
                    ae[mt][3] = be1 + pr[mt][1][0]*Fc[n0+1] + pr[mt][1][1]*Fc[NW+n0+1] + pr[mt][1][2]*Fc[2*NW+n0+1];
                    ao[mt][0] = bq0 + pr[mt][0][0]*Fc[n1]   + pr[mt][0][1]*Fc[NW+n1]   + pr[mt][0][2]*Fc[2*NW+n1];
                    ao[mt][1] = bq1 + pr[mt][0][0]*Fc[n1+1] + pr[mt][0][1]*Fc[NW+n1+1] + pr[mt][0][2]*Fc[2*NW+n1+1];
                    ao[mt][2] = bq0 + pr[mt][1][0]*Fc[n1]   + pr[mt][1][1]*Fc[NW+n1]   + pr[mt][1][2]*Fc[2*NW+n1];
                    ao[mt][3] = bq1 + pr[mt][1][0]*Fc[n1+1] + pr[mt][1][1]*Fc[NW+n1+1] + pr[mt][1][2]*Fc[2*NW+n1+1];
                } else {
                    ae[mt][0] = be0; ae[mt][1] = be1; ae[mt][2] = be0; ae[mt][3] = be1;
                    ao[mt][0] = bq0; ao[mt][1] = bq1; ao[mt][2] = bq0; ao[mt][3] = bq1;
                }
            }
        }
#pragma unroll
        for (int kt = 0; kt < 8; kt++) {
            uint32_t B4[4];
            ldsm_x4(B4, rowb + (uint32_t)((((kt << 1) + gk) ^ sw) << 4));
            mma16816(ae[0], A[0][kt], &B4[0]);
            mma16816(ao[0], A[0][kt], &B4[2]);
            mma16816(ae[1], A[1][kt], &B4[0]);
            mma16816(ao[1], A[1][kt], &B4[2]);
        }
        __half2 h;
#pragma unroll
        for (int mt = 0; mt < 2; mt++) {
            h = __floats2half2_rn(fmaxf(ae[mt][0], 0.f), fmaxf(ae[mt][1], 0.f)); An[mt][np][0] = *(uint32_t*)&h;
            h = __floats2half2_rn(fmaxf(ae[mt][2], 0.f), fmaxf(ae[mt][3], 0.f)); An[mt][np][1] = *(uint32_t*)&h;
            h = __floats2half2_rn(fmaxf(ao[mt][0], 0.f), fmaxf(ao[mt][1], 0.f)); An[mt][np][2] = *(uint32_t*)&h;
            h = __floats2half2_rn(fmaxf(ao[mt][2], 0.f), fmaxf(ao[mt][3], 0.f)); An[mt][np][3] = *(uint32_t*)&h;
        }
    }
}

// ---------------------------------------------------------------------------
// main kernel
// ---------------------------------------------------------------------------
__global__ void __launch_bounds__(NT, 1) nerf_hmma_kernel(
    const float* __restrict__ x,
    const float* __restrict__ w0, const float* __restrict__ b0,
    const float* __restrict__ b1, const float* __restrict__ b2,
    const float* __restrict__ b3, const float* __restrict__ bd,
    const float* __restrict__ bf, const float* __restrict__ br,
    const float* __restrict__ bo, const float* __restrict__ w2,
    const float* __restrict__ wr, const float* __restrict__ wd,
    const float* __restrict__ wo, float* __restrict__ out)
{
    extern __shared__ char smem[];
    const uint32_t sb = smem_u32(smem);
    float* F = (float*)(smem + OFF_F);

    const int tid = threadIdx.x;
    const int w = tid >> 5, lane = tid & 31;
    const int q = lane >> 2;               // row-in-8 for this quad
    const int s0 = blockIdx.x * TILE_M;

    // ---- kick off async weight staging (fp16 prepped, contiguous 144KB) ----
    {
        uint64_t gw;
        asm("cvta.to.global.u64 %0, %1;" : "=l"(gw) : "l"((const void*)g_BW));
        for (int i = tid * 16; i < 147456; i += NT * 16)
            CP_ASYNC16(sb + OFF_W1 + (uint32_t)i, gw + (uint64_t)i);
        CP_COMMIT();
    }

    // ---- stage misc fp32 params + inputs ----
    for (int i = tid; i < 128; i += NT) {
        F[FB0 + i] = b0[i]; F[FB1 + i] = b1[i]; F[FB2 + i] = b2[i];
        F[FB3 + i] = b3[i]; F[FBF + i] = bf[i]; F[FWD + i] = wd[i];
    }
    for (int i = tid; i < 64; i += NT) F[FBR + i] = br[i];
    for (int i = tid; i < 384; i += NT) { F[FW0 + i] = w0[i]; F[FW2B + i] = w2[128 * 128 + i]; }
    for (int i = tid; i < 192; i += NT) { F[FWRB + i] = wr[128 * 64 + i]; F[FWO + i] = wo[i]; }
    if (tid == 0) { F[FBD] = bd[0]; F[FBO] = bo[0]; F[FBO + 1] = bo[1]; F[FBO + 2] = bo[2]; }
    for (int i = tid; i < TILE_M * 6; i += NT) {
        int r = i / 6, c = i % 6;
        float v = x[(size_t)(s0 + r) * 6 + c];
        if (c < 3) F[FPOS + c * 256 + r] = v; else F[FVIEW + (c - 3) * 256 + r] = v;
    }
    __syncthreads();

    uint32_t A0[2][8][4], A1[2][8][4];

    // ---- Layer 0 (K=3) via FFMA directly into A fragments ----
    {
        float px[2][2], py[2][2], pz[2][2];
#pragma unroll
        for (int mt = 0; mt < 2; mt++)
#pragma unroll
            for (int hf = 0; hf < 2; hf++) {
                int r = w * 32 + mt * 16 + hf * 8 + q;
                px[mt][hf] = F[FPOS + r]; py[mt][hf] = F[FPOS + 256 + r]; pz[mt][hf] = F[FPOS + 512 + r];
            }
        const int cbase = 2 * (lane & 3);
#pragma unroll
        for (int kt = 0; kt < 8; kt++) {
            float Bv[4], Wx[4], Wy[4], Wz[4];
#pragma unroll
            for (int j = 0; j < 4; j++) {
                int c = kt * 16 + cbase + (j >> 1) * 8 + (j & 1);
                Bv[j] = F[FB0 + c]; Wx[j] = F[FW0 + c]; Wy[j] = F[FW0 + 128 + c]; Wz[j] = F[FW0 + 256 + c];
            }
#pragma unroll
            for (int mt = 0; mt < 2; mt++)
#pragma unroll
                for (int hf = 0; hf < 2; hf++) {
                    float v0 = fmaxf(Bv[0] + px[mt][hf]*Wx[0] + py[mt][hf]*Wy[0] + pz[mt][hf]*Wz[0], 0.f);
                    float v1 = fmaxf(Bv[1] + px[mt][hf]*Wx[1] + py[mt][hf]*Wy[1] + pz[mt][hf]*Wz[1], 0.f);
                    float v8 = fmaxf(Bv[2] + px[mt][hf]*Wx[2] + py[mt][hf]*Wy[2] + pz[mt][hf]*Wz[2], 0.f);
                    float v9 = fmaxf(Bv[3] + px[mt][hf]*Wx[3] + py[mt][hf]*Wy[3] + pz[mt][hf]*Wz[3], 0.f);
                    __half2 lo = __floats2half2_rn(v0, v1), hi = __floats2half2_rn(v8, v9);
                    A0[mt][kt][hf]     = *(uint32_t*)&lo;
                    A0[mt][kt][2 + hf] = *(uint32_t*)&hi;
                }
        }
    }

    // ---- weights ready? ----
    CP_WAIT0();
    __syncthreads();

    float posr[2][2][3], viewr[2][2][3];
#pragma unroll
    for (int mt = 0; mt < 2; mt++)
#pragma unroll
        for (int hf = 0; hf < 2; hf++) {
            int r = w * 32 + mt * 16 + hf * 8 + q;
            posr[mt][hf][0] = F[FPOS + r];        posr[mt][hf][1] = F[FPOS + 256 + r];
            posr[mt][hf][2] = F[FPOS + 512 + r];
            viewr[mt][hf][0] = F[FVIEW + r];      viewr[mt][hf][1] = F[FVIEW + 256 + r];
            viewr[mt][hf][2] = F[FVIEW + 512 + r];
        }

    // ---- mainloop: NO __syncthreads, activations stay in registers ----
    run_layer<8, false>(A0, A1, sb + OFF_W1,               F + FB1, F, posr, lane);          // h1
    run_layer<8, true >(A1, A0, sb + OFF_W1 + GW_W2 * 2,   F + FB2, F + FW2B, posr, lane);   // h2 (+pos)
    run_layer<8, false>(A0, A1, sb + OFF_W1 + GW_W3 * 2,   F + FB3, F, posr, lane);          // h3

    // ---- density head from h3 (A1) ----
    {
        const float bdv = F[FBD];
        const int cbase = 2 * (lane & 3);
#pragma unroll
        for (int mt = 0; mt < 2; mt++) {
            float d0 = 0.f, d1 = 0.f;
#pragma unroll
            for (int kt = 0; kt < 8; kt++) {
                int k0 = kt * 16 + cbase;
                float2 wlo = *(const float2*)&F[FWD + k0];
                float2 whi = *(const float2*)&F[FWD + k0 + 8];
                float2 f0 = __half22float2(*(__half2*)&A1[mt][kt][0]);
                float2 f1 = __half22float2(*(__half2*)&A1[mt][kt][1]);
                float2 f2 = __half22float2(*(__half2*)&A1[mt][kt][2]);
                float2 f3 = __half22float2(*(__half2*)&A1[mt][kt][3]);
                d0 += f0.x * wlo.x + f0.y * wlo.y + f2.x * whi.x + f2.y * whi.y;
                d1 += f1.x * wlo.x + f1.y * wlo.y + f3.x * whi.x + f3.y * whi.y;
            }
            d0 += __shfl_xor_sync(0xffffffffu, d0, 1); d0 += __shfl_xor_sync(0xffffffffu, d0, 2);
            d1 += __shfl_xor_sync(0xffffffffu, d1, 1); d1 += __shfl_xor_sync(0xffffffffu, d1, 2);
            if ((lane & 3) == 0) {
                int Ra = s0 + w * 32 + mt * 16 + q;
                out[3 * S_TOTAL + Ra]     = fmaxf(d0 + bdv, 0.f);
                out[3 * S_TOTAL + Ra + 8] = fmaxf(d1 + bdv, 0.f);
            }
        }
    }

    run_layer<8, false>(A1, A0, sb + OFF_W1 + GW_WF * 2,   F + FBF, F, posr, lane);          // features
    run_layer<4, true >(A0, A1, sb + OFF_W1 + GW_WR * 2,   F + FBR, F + FWRB, viewr, lane);  // r (+view)

    // ---- rgb head from r (A1, k-tiles 0..3) ----
    {
        const int cbase = 2 * (lane & 3);
#pragma unroll
        for (int mt = 0; mt < 2; mt++) {
            float s[2][3] = {{0.f,0.f,0.f},{0.f,0.f,0.f}};
#pragma unroll
            for (int kt = 0; kt < 4; kt++) {
                int k0 = kt * 16 + cbase, k8 = k0 + 8;
                float2 f0 = __half22float2(*(__half2*)&A1[mt][kt][0]);
                float2 f1 = __half22float2(*(__half2*)&A1[mt][kt][1]);
                float2 f2 = __half22float2(*(__half2*)&A1[mt][kt][2]);
                float2 f3 = __half22float2(*(__half2*)&A1[mt][kt][3]);
#pragma unroll
                for (int c = 0; c < 3; c++) {
                    float w00 = F[FWO + k0 * 3 + c],       w01 = F[FWO + (k0 + 1) * 3 + c];
                    float w08 = F[FWO + k8 * 3 + c],       w09 = F[FWO + (k8 + 1) * 3 + c];
                    s[0][c] += f0.x * w00 + f0.y * w01 + f2.x * w08 + f2.y * w09;
                    s[1][c] += f1.x * w00 + f1.y * w01 + f3.x * w08 + f3.y * w09;
                }
            }
#pragma unroll
            for (int hf = 0; hf < 2; hf++)
#pragma unroll
                for (int c = 0; c < 3; c++) {
                    s[hf][c] += __shfl_xor_sync(0xffffffffu, s[hf][c], 1);
                    s[hf][c] += __shfl_xor_sync(0xffffffffu, s[hf][c], 2);
                }
            if ((lane & 3) == 0) {
                int Ra = s0 + w * 32 + mt * 16 + q;
#pragma unroll
                for (int hf = 0; hf < 2; hf++) {
                    size_t o = (size_t)(Ra + hf * 8) * 3;
                    out[o + 0] = 1.f / (1.f + expf(-(s[hf][0] + F[FBO])));
                    out[o + 1] = 1.f / (1.f + expf(-(s[hf][1] + F[FBO + 1])));
                    out[o + 2] = 1.f / (1.f + expf(-(s[hf][2] + F[FBO + 2])));
                }
            }
        }
    }
}

extern "C" void kernel_launch(void* const* d_in, const int* in_sizes, int n_in,
                              void* d_out, int out_size) {
    (void)in_sizes; (void)n_in; (void)out_size;
    const float* x  = (const float*)d_in[0];
    const float* w0 = (const float*)d_in[1];  const float* b0 = (const float*)d_in[2];
    const float* w1 = (const float*)d_in[3];  const float* b1 = (const float*)d_in[4];
    const float* w2 = (const float*)d_in[5];  const float* b2 = (const float*)d_in[6];
    const float* w3 = (const float*)d_in[7];  const float* b3 = (const float*)d_in[8];
    const float* wd = (const float*)d_in[9];  const float* bd = (const float*)d_in[10];
    const float* wf = (const float*)d_in[11]; const float* bf = (const float*)d_in[12];
    const float* wr = (const float*)d_in[13]; const float* br = (const float*)d_in[14];
    const float* wo = (const float*)d_in[15]; const float* bo = (const float*)d_in[16];
    float* out = (float*)d_out;

    prep_weights<<<288, 256>>>(w1, w2, w3, wf, wr);

    cudaFuncSetAttribute(nerf_hmma_kernel,
                         cudaFuncAttributeMaxDynamicSharedMemorySize, SMEM_TOTAL);
    nerf_hmma_kernel<<<S_TOTAL / TILE_M, NT, SMEM_TOTAL>>>(
        x, w0, b0, b1, b2, b3, bd, bf, br, bo, w2, wr, wd, wo, out);
}

// round 16
// speedup vs baseline: 1.2288x; 1.1225x over previous
#include <cuda_runtime.h>
#include <cuda_fp16.h>
#include <cstdint>
#include <math.h>

#define N_RAYS   4096
#define N_SAMP   192
#define S_TOTAL  (N_RAYS * N_SAMP)   // 786432
#define TILE_M   256
#define NTILES   (S_TOTAL / TILE_M)  // 3072
#define NT       256                 // 8 warps, 32 rows each
#define GRIDX    148                 // persistent: 1 CTA per SM

// ---------------------------------------------------------------------------
// helpers
// ---------------------------------------------------------------------------
__device__ __forceinline__ uint32_t smem_u32(const void* p) {
    uint32_t a;
    asm("{ .reg .u64 t; cvta.to.shared.u64 t, %1; cvt.u32.u64 %0, t; }" : "=r"(a) : "l"(p));
    return a;
}

__device__ __forceinline__ void ldsm_x4(uint32_t* r, uint32_t addr) {
    asm volatile("ldmatrix.sync.aligned.m8n8.x4.shared.b16 {%0,%1,%2,%3}, [%4];"
        : "=r"(r[0]), "=r"(r[1]), "=r"(r[2]), "=r"(r[3]) : "r"(addr));
}

__device__ __forceinline__ void mma16816(float* c, const uint32_t* a, const uint32_t* b) {
    asm volatile("mma.sync.aligned.m16n8k16.row.col.f32.f16.f16.f32 "
        "{%0,%1,%2,%3}, {%4,%5,%6,%7}, {%8,%9}, {%0,%1,%2,%3};"
        : "+f"(c[0]), "+f"(c[1]), "+f"(c[2]), "+f"(c[3])
        : "r"(a[0]), "r"(a[1]), "r"(a[2]), "r"(a[3]), "r"(b[0]), "r"(b[1]));
}

#define CP_ASYNC16(dst, src) \
    asm volatile("cp.async.cg.shared.global [%0], [%1], 16;" :: "r"(dst), "l"(src) : "memory")
#define CP_COMMIT()  asm volatile("cp.async.commit_group;" ::: "memory")
#define CP_WAIT0()   asm volatile("cp.async.wait_group 0;" ::: "memory")

// ---------------------------------------------------------------------------
// Prepared weights: fp16, B^T layout: Bt[n][k] = W[k][n], row = 256B,
// k-chunk (16B) XOR-swizzled by (n&7) for conflict-free ldmatrix.
// ---------------------------------------------------------------------------
#define GW_W1 0
#define GW_W2 16384
#define GW_W3 32768
#define GW_WF 49152
#define GW_WR 65536
__device__ __align__(16) unsigned short g_BW[73728];

__device__ __forceinline__ uint32_t bt_off(int n, int k) {   // byte offset
    return (uint32_t)(n * 256) + (uint32_t)(((((k >> 3) ^ (n & 7))) << 4) + ((k & 7) << 1));
}

__global__ void prep_weights(const float* __restrict__ w1, const float* __restrict__ w2,
                             const float* __restrict__ w3, const float* __restrict__ wf,
                             const float* __restrict__ wr) {
    int e = blockIdx.x * blockDim.x + threadIdx.x;
    if (e < 65536) {
        int m = e >> 14, r = e & 16383;
        int k = r >> 7, n = r & 127;
        const float* W = (m == 0) ? w1 : (m == 1) ? w2 : (m == 2) ? w3 : wf;
        g_BW[m * 16384 + (bt_off(n, k) >> 1)] = __half_as_ushort(__float2half_rn(W[k * 128 + n]));
    } else if (e < 73728) {
        int r = e - 65536;
        int k = r >> 6, n = r & 63;
        g_BW[GW_WR + (bt_off(n, k) >> 1)] = __half_as_ushort(__float2half_rn(wr[k * 64 + n]));
    }
}

// ---------------------------------------------------------------------------
// smem layout
// ---------------------------------------------------------------------------
#define OFF_F      16
#define OFF_W1     24576
#define SMEM_TOTAL (24576 + 147456)    // 168 KB

// float-region indices (relative to F)
#define FB0   0
#define FB1   128
#define FB2   256
#define FB3   384
#define FBF   512
#define FBR   640
#define FW0   704     // [3][128]
#define FW2B  1088    // [3][128]
#define FWRB  1472    // [3][64]
#define FWD   1664    // [128]
#define FWO   1792    // [64][3]
#define FBD   1984
#define FBO   1985    // 3
#define FXB0  2048    // raw x tile buf 0: [256][6] floats
#define FXB1  3584    // raw x tile buf 1

// ---------------------------------------------------------------------------
// Fused layer: act(regs, 32 rows as 2 m-tiles) @ Bt(smem) + bias (+concat),
// ReLU, repack. NP = N/16. K = 128 (8 k-tiles).
// ---------------------------------------------------------------------------
template <int NP, bool CONCAT>
__device__ __forceinline__ void run_layer(
    const uint32_t (&A)[2][8][4], uint32_t (&An)[2][8][4],
    uint32_t wsm, const float* __restrict__ Fb,
    const float* __restrict__ Fc, const float (&pr)[2][2][3], int lane)
{
    const int g  = lane >> 3, ln = lane & 7;
    const int nl = ((g >> 1) << 3) + ln;   // n offset within 16-wide pair
    const int gk = g & 1;                  // k-chunk select (lo/hi 8)
    const int cb = 2 * (lane & 3);
    constexpr int NW = NP * 16;
#pragma unroll
    for (int np = 0; np < NP; np++) {
        const int n_abs = np * 16 + nl;
        const uint32_t rowb = wsm + ((uint32_t)n_abs << 8);
        const int sw = n_abs & 7;
        const int n0 = np * 16 + cb, n1 = n0 + 8;
        float ae[2][4], ao[2][4];
        {
            float be0 = Fb[n0], be1 = Fb[n0 + 1], bq0 = Fb[n1], bq1 = Fb[n1 + 1];
#pragma unroll
            for (int mt = 0; mt < 2; mt++) {
                if constexpr (CONCAT) {
                    ae[mt][0] = be0 + pr[mt][0][0]*Fc[n0]   + pr[mt][0][1]*Fc[NW+n0]   + pr[mt][0][2]*Fc[2*NW+n0];
                    ae[mt][1] = be1 + pr[mt][0][0]*Fc[n0+1] + pr[mt][0][1]*Fc[NW+n0+1] + pr[mt][0][2]*Fc[2*NW+n0+1];
                    ae[mt][2] = be0 + pr[mt][1][0]*Fc[n0]   + pr[mt][1][1]*Fc[NW+n0]   + pr[mt][1][2]*Fc[2*NW+n0];
                    ae[mt][3] = be1 + pr[mt][1][0]*Fc[n0+1] + pr[mt][1][1]*Fc[NW+n0+1] + pr[mt][1][2]*Fc[2*NW+n0+1];
                    ao[mt][0] = bq0 + pr[mt][0][0]*Fc[n1]   + pr[mt][0][1]*Fc[NW+n1]   + pr[mt][0][2]*Fc[2*NW+n1];
                    ao[mt][1] = bq1 + pr[mt][0][0]*Fc[n1+1] + pr[mt][0][1]*Fc[NW+n1+1] + pr[mt][0][2]*Fc[2*NW+n1+1];
                    ao[mt][2] = bq0 + pr[mt][1][0]*Fc[n1]   + pr[mt][1][1]*Fc[NW+n1]   + pr[mt][1][2]*Fc[2*NW+n1];
                    ao[mt][3] = bq1 + pr[mt][1][0]*Fc[n1+1] + pr[mt][1][1]*Fc[NW+n1+1] + pr[mt][1][2]*Fc[2*NW+n1+1];
                } else {
                    ae[mt][0] = be0; ae[mt][1] = be1; ae[mt][2] = be0; ae[mt][3] = be1;
                    ao[mt][0] = bq0; ao[mt][1] = bq1; ao[mt][2] = bq0; ao[mt][3] = bq1;
                }
            }
        }
#pragma unroll
        for (int kt = 0; kt < 8; kt++) {
            uint32_t B4[4];
            ldsm_x4(B4, rowb + (uint32_t)((((kt << 1) + gk) ^ sw) << 4));
            mma16816(ae[0], A[0][kt], &B4[0]);
            mma16816(ao[0], A[0][kt], &B4[2]);
            mma16816(ae[1], A[1][kt], &B4[0]);
            mma16816(ao[1], A[1][kt], &B4[2]);
        }
        __half2 h;
#pragma unroll
        for (int mt = 0; mt < 2; mt++) {
            h = __floats2half2_rn(fmaxf(ae[mt][0], 0.f), fmaxf(ae[mt][1], 0.f)); An[mt][np][0] = *(uint32_t*)&h;
            h = __floats2half2_rn(fmaxf(ae[mt][2], 0.f), fmaxf(ae[mt][3], 0.f)); An[mt][np][1] = *(uint32_t*)&h;
            h = __floats2half2_rn(fmaxf(ao[mt][0], 0.f), fmaxf(ao[mt][1], 0.f)); An[mt][np][2] = *(uint32_t*)&h;
            h = __floats2half2_rn(fmaxf(ao[mt][2], 0.f), fmaxf(ao[mt][3], 0.f)); An[mt][np][3] = *(uint32_t*)&h;
        }
    }
}

// ---------------------------------------------------------------------------
// persistent kernel: weights staged once, tiles looped with x double-buffer
// ---------------------------------------------------------------------------
__global__ void __launch_bounds__(NT, 1) nerf_hmma_kernel(
    const float* __restrict__ x,
    const float* __restrict__ w0, const float* __restrict__ b0,
    const float* __restrict__ b1, const float* __restrict__ b2,
    const float* __restrict__ b3, const float* __restrict__ bd,
    const float* __restrict__ bf, const float* __restrict__ br,
    const float* __restrict__ bo, const float* __restrict__ w2,
    const float* __restrict__ wr, const float* __restrict__ wd,
    const float* __restrict__ wo, float* __restrict__ out)
{
    extern __shared__ char smem[];
    const uint32_t sb = smem_u32(smem);
    float* F = (float*)(smem + OFF_F);

    const int tid = threadIdx.x;
    const int w = tid >> 5, lane = tid & 31;
    const int q = lane >> 2;               // row-in-8 for this quad

    // ---- stage weights (once) + first x tile via cp.async ----
    {
        uint64_t gw;
        asm("cvta.to.global.u64 %0, %1;" : "=l"(gw) : "l"((const void*)g_BW));
        for (int i = tid * 16; i < 147456; i += NT * 16)
            CP_ASYNC16(sb + OFF_W1 + (uint32_t)i, gw + (uint64_t)i);
        uint64_t gx = (uint64_t)(const char*)x + (uint64_t)blockIdx.x * (TILE_M * 24);
        for (int i = tid * 16; i < TILE_M * 24; i += NT * 16)
            CP_ASYNC16(sb + OFF_F + FXB0 * 4 + (uint32_t)i, gx + (uint64_t)i);
        CP_COMMIT();
    }

    // ---- stage misc fp32 params ----
    for (int i = tid; i < 128; i += NT) {
        F[FB0 + i] = b0[i]; F[FB1 + i] = b1[i]; F[FB2 + i] = b2[i];
        F[FB3 + i] = b3[i]; F[FBF + i] = bf[i]; F[FWD + i] = wd[i];
    }
    for (int i = tid; i < 64; i += NT) F[FBR + i] = br[i];
    for (int i = tid; i < 384; i += NT) { F[FW0 + i] = w0[i]; F[FW2B + i] = w2[128 * 128 + i]; }
    for (int i = tid; i < 192; i += NT) { F[FWRB + i] = wr[128 * 64 + i]; F[FWO + i] = wo[i]; }
    if (tid == 0) { F[FBD] = bd[0]; F[FBO] = bo[0]; F[FBO + 1] = bo[1]; F[FBO + 2] = bo[2]; }

    const int cbase = 2 * (lane & 3);
    int buf = 0;

    for (int t = blockIdx.x; t < NTILES; t += GRIDX, buf ^= 1) {
        // wait for this tile's x (first iter: also weights); sync; prefetch next tile's x
        CP_WAIT0();
        __syncthreads();
        {
            int tn = t + GRIDX;
            if (tn < NTILES) {
                uint64_t gx = (uint64_t)(const char*)x + (uint64_t)tn * (TILE_M * 24);
                uint32_t db = sb + OFF_F + (uint32_t)((buf ? FXB0 : FXB1) * 4);
                for (int i = tid * 16; i < TILE_M * 24; i += NT * 16)
                    CP_ASYNC16(db + (uint32_t)i, gx + (uint64_t)i);
                CP_COMMIT();
            }
        }
        const float* X = F + (buf ? FXB1 : FXB0);
        const int s0 = t * TILE_M;

        uint32_t A0[2][8][4], A1[2][8][4];
        float pr[2][2][3];     // pos or view rows, reloaded per use

        // ---- Layer 0 (K=3) via FFMA directly into A fragments ----
#pragma unroll
        for (int mt = 0; mt < 2; mt++)
#pragma unroll
            for (int hf = 0; hf < 2; hf++) {
                int r = w * 32 + mt * 16 + hf * 8 + q;
                pr[mt][hf][0] = X[r * 6]; pr[mt][hf][1] = X[r * 6 + 1]; pr[mt][hf][2] = X[r * 6 + 2];
            }
#pragma unroll
        for (int kt = 0; kt < 8; kt++) {
            float Bv[4], Wx[4], Wy[4], Wz[4];
#pragma unroll
            for (int j = 0; j < 4; j++) {
                int c = kt * 16 + cbase + (j >> 1) * 8 + (j & 1);
                Bv[j] = F[FB0 + c]; Wx[j] = F[FW0 + c]; Wy[j] = F[FW0 + 128 + c]; Wz[j] = F[FW0 + 256 + c];
            }
#pragma unroll
            for (int mt = 0; mt < 2; mt++)
#pragma unroll
                for (int hf = 0; hf < 2; hf++) {
                    float v0 = fmaxf(Bv[0] + pr[mt][hf][0]*Wx[0] + pr[mt][hf][1]*Wy[0] + pr[mt][hf][2]*Wz[0], 0.f);
                    float v1 = fmaxf(Bv[1] + pr[mt][hf][0]*Wx[1] + pr[mt][hf][1]*Wy[1] + pr[mt][hf][2]*Wz[1], 0.f);
                    float v8 = fmaxf(Bv[2] + pr[mt][hf][0]*Wx[2] + pr[mt][hf][1]*Wy[2] + pr[mt][hf][2]*Wz[2], 0.f);
                    float v9 = fmaxf(Bv[3] + pr[mt][hf][0]*Wx[3] + pr[mt][hf][1]*Wy[3] + pr[mt][hf][2]*Wz[3], 0.f);
                    __half2 lo = __floats2half2_rn(v0, v1), hi = __floats2half2_rn(v8, v9);
                    A0[mt][kt][hf]     = *(uint32_t*)&lo;
                    A0[mt][kt][2 + hf] = *(uint32_t*)&hi;
                }
        }

        // ---- mainloop (pr currently holds pos rows) ----
        run_layer<8, false>(A0, A1, sb + OFF_W1,             F + FB1, F, pr, lane);          // h1
        run_layer<8, true >(A1, A0, sb + OFF_W1 + GW_W2 * 2, F + FB2, F + FW2B, pr, lane);   // h2 (+pos)
        run_layer<8, false>(A0, A1, sb + OFF_W1 + GW_W3 * 2, F + FB3, F, pr, lane);          // h3

        // ---- density head from h3 (A1) ----
        {
            const float bdv = F[FBD];
#pragma unroll
            for (int mt = 0; mt < 2; mt++) {
                float d0 = 0.f, d1 = 0.f;
#pragma unroll
                for (int kt = 0; kt < 8; kt++) {
                    int k0 = kt * 16 + cbase;
                    float2 wlo = *(const float2*)&F[FWD + k0];
                    float2 whi = *(const float2*)&F[FWD + k0 + 8];
                    float2 f0 = __half22float2(*(__half2*)&A1[mt][kt][0]);
                    float2 f1 = __half22float2(*(__half2*)&A1[mt][kt][1]);
                    float2 f2 = __half22float2(*(__half2*)&A1[mt][kt][2]);
                    float2 f3 = __half22float2(*(__half2*)&A1[mt][kt][3]);
                    d0 += f0.x * wlo.x + f0.y * wlo.y + f2.x * whi.x + f2.y * whi.y;
                    d1 += f1.x * wlo.x + f1.y * wlo.y + f3.x * whi.x + f3.y * whi.y;
                }
                d0 += __shfl_xor_sync(0xffffffffu, d0, 1); d0 += __shfl_xor_sync(0xffffffffu, d0, 2);
                d1 += __shfl_xor_sync(0xffffffffu, d1, 1); d1 += __shfl_xor_sync(0xffffffffu, d1, 2);
                if ((lane & 3) == 0) {
                    int Ra = s0 + w * 32 + mt * 16 + q;
                    out[3 * S_TOTAL + Ra]     = fmaxf(d0 + bdv, 0.f);
                    out[3 * S_TOTAL + Ra + 8] = fmaxf(d1 + bdv, 0.f);
                }
            }
        }

        // ---- reload pr with view rows; features + r-layer ----
#pragma unroll
        for (int mt = 0; mt < 2; mt++)
#pragma unroll
            for (int hf = 0; hf < 2; hf++) {
                int r = w * 32 + mt * 16 + hf * 8 + q;
                pr[mt][hf][0] = X[r * 6 + 3]; pr[mt][hf][1] = X[r * 6 + 4]; pr[mt][hf][2] = X[r * 6 + 5];
            }
        run_layer<8, false>(A1, A0, sb + OFF_W1 + GW_WF * 2, F + FBF, F, pr, lane);          // features
        run_layer<4, true >(A0, A1, sb + OFF_W1 + GW_WR * 2, F + FBR, F + FWRB, pr, lane);   // r (+view)

        // ---- rgb head from r (A1, k-tiles 0..3) ----
        {
#pragma unroll
            for (int mt = 0; mt < 2; mt++) {
                float s[2][3] = {{0.f,0.f,0.f},{0.f,0.f,0.f}};
#pragma unroll
                for (int kt = 0; kt < 4; kt++) {
                    int k0 = kt * 16 + cbase, k8 = k0 + 8;
                    float2 f0 = __half22float2(*(__half2*)&A1[mt][kt][0]);
                    float2 f1 = __half22float2(*(__half2*)&A1[mt][kt][1]);
                    float2 f2 = __half22float2(*(__half2*)&A1[mt][kt][2]);
                    float2 f3 = __half22float2(*(__half2*)&A1[mt][kt][3]);
#pragma unroll
                    for (int c = 0; c < 3; c++) {
                        float w00 = F[FWO + k0 * 3 + c],       w01 = F[FWO + (k0 + 1) * 3 + c];
                        float w08 = F[FWO + k8 * 3 + c],       w09 = F[FWO + (k8 + 1) * 3 + c];
                        s[0][c] += f0.x * w00 + f0.y * w01 + f2.x * w08 + f2.y * w09;
                        s[1][c] += f1.x * w00 + f1.y * w01 + f3.x * w08 + f3.y * w09;
                    }
                }
#pragma unroll
                for (int hf = 0; hf < 2; hf++)
#pragma unroll
                    for (int c = 0; c < 3; c++) {
                        s[hf][c] += __shfl_xor_sync(0xffffffffu, s[hf][c], 1);
                        s[hf][c] += __shfl_xor_sync(0xffffffffu, s[hf][c], 2);
                    }
                if ((lane & 3) == 0) {
                    int Ra = s0 + w * 32 + mt * 16 + q;
#pragma unroll
                    for (int hf = 0; hf < 2; hf++) {
                        size_t o = (size_t)(Ra + hf * 8) * 3;
                        out[o + 0] = 1.f / (1.f + expf(-(s[hf][0] + F[FBO])));
                        out[o + 1] = 1.f / (1.f + expf(-(s[hf][1] + F[FBO + 1])));
                        out[o + 2] = 1.f / (1.f + expf(-(s[hf][2] + F[FBO + 2])));
                    }
                }
            }
        }
    }
}

extern "C" void kernel_launch(void* const* d_in, const int* in_sizes, int n_in,
                              void* d_out, int out_size) {
    (void)in_sizes; (void)n_in; (void)out_size;
    const float* x  = (const float*)d_in[0];
    const float* w0 = (const float*)d_in[1];  const float* b0 = (const float*)d_in[2];
    const float* w1 = (const float*)d_in[3];  const float* b1 = (const float*)d_in[4];
    const float* w2 = (const float*)d_in[5];  const float* b2 = (const float*)d_in[6];
    const float* w3 = (const float*)d_in[7];  const float* b3 = (const float*)d_in[8];
    const float* wd = (const float*)d_in[9];  const float* bd = (const float*)d_in[10];
    const float* wf = (const float*)d_in[11]; const float* bf = (const float*)d_in[12];
    const float* wr = (const float*)d_in[13]; const float* br = (const float*)d_in[14];
    const float* wo = (const float*)d_in[15]; const float* bo = (const float*)d_in[16];
    float* out = (float*)d_out;

    prep_weights<<<288, 256>>>(w1, w2, w3, wf, wr);

    cudaFuncSetAttribute(nerf_hmma_kernel,
                         cudaFuncAttributeMaxDynamicSharedMemorySize, SMEM_TOTAL);
    nerf_hmma_kernel<<<GRIDX, NT, SMEM_TOTAL>>>(
        x, w0, b0, b1, b2, b3, bd, bf, br, bo, w2, wr, wd, wo, out);
}

// round 17
// speedup vs baseline: 1.2904x; 1.0501x over previous
#include <cuda_runtime.h>
#include <cuda_fp16.h>
#include <cstdint>
#include <math.h>

#define N_RAYS   4096
#define N_SAMP   192
#define S_TOTAL  (N_RAYS * N_SAMP)   // 786432
#define TILE_M   256
#define NTILES   (S_TOTAL / TILE_M)  // 3072
#define NT       256                 // 8 warps, 32 rows each
#define GRIDX    148                 // persistent: 1 CTA per SM

// ---------------------------------------------------------------------------
// helpers
// ---------------------------------------------------------------------------
__device__ __forceinline__ uint32_t smem_u32(const void* p) {
    uint32_t a;
    asm("{ .reg .u64 t; cvta.to.shared.u64 t, %1; cvt.u32.u64 %0, t; }" : "=r"(a) : "l"(p));
    return a;
}

__device__ __forceinline__ void ldsm_x4(uint32_t* r, uint32_t addr) {
    asm volatile("ldmatrix.sync.aligned.m8n8.x4.shared.b16 {%0,%1,%2,%3}, [%4];"
        : "=r"(r[0]), "=r"(r[1]), "=r"(r[2]), "=r"(r[3]) : "r"(addr));
}

__device__ __forceinline__ void mma16816(float* c, const uint32_t* a, const uint32_t* b) {
    asm volatile("mma.sync.aligned.m16n8k16.row.col.f32.f16.f16.f32 "
        "{%0,%1,%2,%3}, {%4,%5,%6,%7}, {%8,%9}, {%0,%1,%2,%3};"
        : "+f"(c[0]), "+f"(c[1]), "+f"(c[2]), "+f"(c[3])
        : "r"(a[0]), "r"(a[1]), "r"(a[2]), "r"(a[3]), "r"(b[0]), "r"(b[1]));
}

#define CP_ASYNC16(dst, src) \
    asm volatile("cp.async.cg.shared.global [%0], [%1], 16;" :: "r"(dst), "l"(src) : "memory")
#define CP_COMMIT()  asm volatile("cp.async.commit_group;" ::: "memory")
#define CP_WAIT0()   asm volatile("cp.async.wait_group 0;" ::: "memory")

// ---------------------------------------------------------------------------
// Prepared weights: fp16, B^T layout: Bt[n][k] = W[k][n], row = 256B,
// k-chunk (16B) XOR-swizzled by (n&7) for conflict-free ldmatrix.
// W1 | W2 | W3 | WF | WR | W0 (W0 has K=16: w0 rows 0..2, bias at k=3)
// ---------------------------------------------------------------------------
#define GW_W1 0
#define GW_W2 16384
#define GW_W3 32768
#define GW_WF 49152
#define GW_WR 65536
#define GW_W0 73728
__device__ __align__(16) unsigned short g_BW[90112];

__device__ __forceinline__ uint32_t bt_off(int n, int k) {   // byte offset
    return (uint32_t)(n * 256) + (uint32_t)(((((k >> 3) ^ (n & 7))) << 4) + ((k & 7) << 1));
}

__global__ void prep_weights(const float* __restrict__ w1, const float* __restrict__ w2,
                             const float* __restrict__ w3, const float* __restrict__ wf,
                             const float* __restrict__ wr, const float* __restrict__ w0,
                             const float* __restrict__ b0) {
    int e = blockIdx.x * blockDim.x + threadIdx.x;
    if (e < 65536) {
        int m = e >> 14, r = e & 16383;
        int k = r >> 7, n = r & 127;
        const float* W = (m == 0) ? w1 : (m == 1) ? w2 : (m == 2) ? w3 : wf;
        g_BW[m * 16384 + (bt_off(n, k) >> 1)] = __half_as_ushort(__float2half_rn(W[k * 128 + n]));
    } else if (e < 73728) {
        int r = e - 65536;
        int k = r >> 6, n = r & 63;
        g_BW[GW_WR + (bt_off(n, k) >> 1)] = __half_as_ushort(__float2half_rn(wr[k * 64 + n]));
    } else if (e < 74240) {
        int r = e - 73728;
        int k = r >> 7, n = r & 127;           // k in 0..3
        float v = (k < 3) ? w0[k * 128 + n] : b0[n];
        g_BW[GW_W0 + (bt_off(n, k) >> 1)] = __half_as_ushort(__float2half_rn(v));
    }
}

// ---------------------------------------------------------------------------
// smem layout
// ---------------------------------------------------------------------------
#define OFF_F      16
#define OFF_W1     24576
#define OFF_W0     (24576 + 147456)            // 172032
#define SMEM_TOTAL (24576 + 147456 + 32768)    // 204800
#define GB_BYTES   180224                      // 90112 shorts

// float-region indices (relative to F)
#define FB1   128
#define FB2   256
#define FB3   384
#define FBF   512
#define FBR   640
#define FW2B  1088    // [3][128]
#define FWRB  1472    // [3][64]
#define FWD   1664    // [128]
#define FWO   1792    // [64][3]
#define FBD   1984
#define FBO   1985    // 3
#define FXB0  2048    // raw x tile buf 0: [256][6] floats
#define FXB1  3584    // raw x tile buf 1

// ---------------------------------------------------------------------------
// Fused layer: act(regs, 32 rows as 2 m-tiles) @ Bt(smem) + bias (+concat),
// ReLU (half2), repack. NP = N/16. K = 128 (8 k-tiles).
// ---------------------------------------------------------------------------
template <int NP, bool CONCAT>
__device__ __forceinline__ void run_layer(
    const uint32_t (&A)[2][8][4], uint32_t (&An)[2][8][4],
    uint32_t wsm, const float* __restrict__ Fb,
    const float* __restrict__ Fc, const float (&pr)[2][2][3],
    const uint32_t (&offs)[8], uint32_t nlsh, int lane)
{
    const int cb = 2 * (lane & 3);
    constexpr int NW = NP * 16;
    const __half2 z2 = __float2half2_rn(0.f);
#pragma unroll
    for (int np = 0; np < NP; np++) {
        const uint32_t rowb = wsm + (uint32_t)(np << 12) + nlsh;
        const int n0 = np * 16 + cb, n1 = n0 + 8;
        float ae[2][4], ao[2][4];
        {
            float be0 = Fb[n0], be1 = Fb[n0 + 1], bq0 = Fb[n1], bq1 = Fb[n1 + 1];
#pragma unroll
            for (int mt = 0; mt < 2; mt++) {
                if constexpr (CONCAT) {
                    ae[mt][0] = be0 + pr[mt][0][0]*Fc[n0]   + pr[mt][0][1]*Fc[NW+n0]   + pr[mt][0][2]*Fc[2*NW+n0];
                    ae[mt][1] = be1 + pr[mt][0][0]*Fc[n0+1] + pr[mt][0][1]*Fc[NW+n0+1] + pr[mt][0][2]*Fc[2*NW+n0+1];
                    ae[mt][2] = be0 + pr[mt][1][0]*Fc[n0]   + pr[mt][1][1]*Fc[NW+n0]   + pr[mt][1][2]*Fc[2*NW+n0];
                    ae[mt][3] = be1 + pr[mt][1][0]*Fc[n0+1] + pr[mt][1][1]*Fc[NW+n0+1] + pr[mt][1][2]*Fc[2*NW+n0+1];
                    ao[mt][0] = bq0 + pr[mt][0][0]*Fc[n1]   + pr[mt][0][1]*Fc[NW+n1]   + pr[mt][0][2]*Fc[2*NW+n1];
                    ao[mt][1] = bq1 + pr[mt][0][0]*Fc[n1+1] + pr[mt][0][1]*Fc[NW+n1+1] + pr[mt][0][2]*Fc[2*NW+n1+1];
                    ao[mt][2] = bq0 + pr[mt][1][0]*Fc[n1]   + pr[mt][1][1]*Fc[NW+n1]   + pr[mt][1][2]*Fc[2*NW+n1];
                    ao[mt][3] = bq1 + pr[mt][1][0]*Fc[n1+1] + pr[mt][1][1]*Fc[NW+n1+1] + pr[mt][1][2]*Fc[2*NW+n1+1];
                } else {
                    ae[mt][0] = be0; ae[mt][1] = be1; ae[mt][2] = be0; ae[mt][3] = be1;
                    ao[mt][0] = bq0; ao[mt][1] = bq1; ao[mt][2] = bq0; ao[mt][3] = bq1;
                }
            }
        }
#pragma unroll
        for (int kt = 0; kt < 8; kt++) {
            uint32_t B4[4];
            ldsm_x4(B4, rowb + offs[kt]);
            mma16816(ae[0], A[0][kt], &B4[0]);
            mma16816(ao[0], A[0][kt], &B4[2]);
            mma16816(ae[1], A[1][kt], &B4[0]);
            mma16816(ao[1], A[1][kt], &B4[2]);
        }
#pragma unroll
        for (int mt = 0; mt < 2; mt++) {
            __half2 h;
            h = __hmax2(__floats2half2_rn(ae[mt][0], ae[mt][1]), z2); An[mt][np][0] = *(uint32_t*)&h;
            h = __hmax2(__floats2half2_rn(ae[mt][2], ae[mt][3]), z2); An[mt][np][1] = *(uint32_t*)&h;
            h = __hmax2(__floats2half2_rn(ao[mt][0], ao[mt][1]), z2); An[mt][np][2] = *(uint32_t*)&h;
            h = __hmax2(__floats2half2_rn(ao[mt][2], ao[mt][3]), z2); An[mt][np][3] = *(uint32_t*)&h;
        }
    }
}

// ---------------------------------------------------------------------------
// persistent kernel: weights staged once, tiles looped with x double-buffer
// ---------------------------------------------------------------------------
__global__ void __launch_bounds__(NT, 1) nerf_hmma_kernel(
    const float* __restrict__ x,
    const float* __restrict__ b1, const float* __restrict__ b2,
    const float* __restrict__ b3, const float* __restrict__ bd,
    const float* __restrict__ bf, const float* __restrict__ br,
    const float* __restrict__ bo, const float* __restrict__ w2,
    const float* __restrict__ wr, const float* __restrict__ wd,
    const float* __restrict__ wo, float* __restrict__ out)
{
    extern __shared__ char smem[];
    const uint32_t sb = smem_u32(smem);
    float* F = (float*)(smem + OFF_F);

    const int tid = threadIdx.x;
    const int w = tid >> 5, lane = tid & 31;
    const int q = lane >> 2;               // row-in-8 for this quad
    const int g = lane >> 3, ln = lane & 7;
    const int gk = g & 1;
    const int nl = ((g >> 1) << 3) + ln;
    const uint32_t nlsh = (uint32_t)(nl << 8);
    uint32_t offs[8];
#pragma unroll
    for (int kt = 0; kt < 8; kt++) offs[kt] = (uint32_t)((((kt << 1) + gk) ^ ln) << 4);

    // ---- stage weights (once, contiguous 176KB) + first x tile ----
    {
        uint64_t gw;
        asm("cvta.to.global.u64 %0, %1;" : "=l"(gw) : "l"((const void*)g_BW));
        for (int i = tid * 16; i < GB_BYTES; i += NT * 16)
            CP_ASYNC16(sb + OFF_W1 + (uint32_t)i, gw + (uint64_t)i);
        uint64_t gx = (uint64_t)(const char*)x + (uint64_t)blockIdx.x * (TILE_M * 24);
        for (int i = tid * 16; i < TILE_M * 24; i += NT * 16)
            CP_ASYNC16(sb + OFF_F + FXB0 * 4 + (uint32_t)i, gx + (uint64_t)i);
        CP_COMMIT();
    }

    // ---- stage misc fp32 params ----
    for (int i = tid; i < 128; i += NT) {
        F[FB1 + i] = b1[i]; F[FB2 + i] = b2[i];
        F[FB3 + i] = b3[i]; F[FBF + i] = bf[i]; F[FWD + i] = wd[i];
    }
    for (int i = tid; i < 64; i += NT) F[FBR + i] = br[i];
    for (int i = tid; i < 384; i += NT) F[FW2B + i] = w2[128 * 128 + i];
    for (int i = tid; i < 192; i += NT) { F[FWRB + i] = wr[128 * 64 + i]; F[FWO + i] = wo[i]; }
    if (tid == 0) { F[FBD] = bd[0]; F[FBO] = bo[0]; F[FBO + 1] = bo[1]; F[FBO + 2] = bo[2]; }

    const int cbase = 2 * (lane & 3);
    const __half2 z2 = __float2half2_rn(0.f);
    int buf = 0;

    for (int t = blockIdx.x; t < NTILES; t += GRIDX, buf ^= 1) {
        // wait for this tile's x (first iter: also weights); sync; prefetch next tile's x
        CP_WAIT0();
        __syncthreads();
        {
            int tn = t + GRIDX;
            if (tn < NTILES) {
                uint64_t gx = (uint64_t)(const char*)x + (uint64_t)tn * (TILE_M * 24);
                uint32_t db = sb + OFF_F + (uint32_t)((buf ? FXB0 : FXB1) * 4);
                for (int i = tid * 16; i < TILE_M * 24; i += NT * 16)
                    CP_ASYNC16(db + (uint32_t)i, gx + (uint64_t)i);
                CP_COMMIT();
            }
        }
        const float* X = F + (buf ? FXB1 : FXB0);
        const int s0 = t * TILE_M;

        uint32_t A0[2][8][4], A1[2][8][4];
        float pr[2][2][3];     // pos or view rows, reloaded per use

#pragma unroll
        for (int mt = 0; mt < 2; mt++)
#pragma unroll
            for (int hf = 0; hf < 2; hf++) {
                int r = w * 32 + mt * 16 + hf * 8 + q;
                pr[mt][hf][0] = X[r * 6]; pr[mt][hf][1] = X[r * 6 + 1]; pr[mt][hf][2] = X[r * 6 + 2];
            }

        // ---- Layer 0 via MMA: A = [px,py,pz,1, 0..], B = W0t (bias folded) ----
        {
            uint32_t Az[2][4];
#pragma unroll
            for (int mt = 0; mt < 2; mt++) {
                __half2 h0, h1;
                if (cbase == 0) {
                    h0 = __floats2half2_rn(pr[mt][0][0], pr[mt][0][1]);
                    h1 = __floats2half2_rn(pr[mt][1][0], pr[mt][1][1]);
                } else if (cbase == 2) {
                    h0 = __floats2half2_rn(pr[mt][0][2], 1.f);
                    h1 = __floats2half2_rn(pr[mt][1][2], 1.f);
                } else {
                    h0 = z2; h1 = z2;
                }
                Az[mt][0] = *(uint32_t*)&h0; Az[mt][1] = *(uint32_t*)&h1;
                Az[mt][2] = 0u;              Az[mt][3] = 0u;
            }
            const uint32_t w0b = sb + OFF_W0 + nlsh + offs[0];
#pragma unroll
            for (int np = 0; np < 8; np++) {
                uint32_t B4[4];
                ldsm_x4(B4, w0b + (uint32_t)(np << 12));
                float ae[2][4] = {{0,0,0,0},{0,0,0,0}}, ao[2][4] = {{0,0,0,0},{0,0,0,0}};
                mma16816(ae[0], Az[0], &B4[0]);
                mma16816(ao[0], Az[0], &B4[2]);
                mma16816(ae[1], Az[1], &B4[0]);
                mma16816(ao[1], Az[1], &B4[2]);
#pragma unroll
                for (int mt = 0; mt < 2; mt++) {
                    __half2 h;
                    h = __hmax2(__floats2half2_rn(ae[mt][0], ae[mt][1]), z2); A0[mt][np][0] = *(uint32_t*)&h;
                    h = __hmax2(__floats2half2_rn(ae[mt][2], ae[mt][3]), z2); A0[mt][np][1] = *(uint32_t*)&h;
                    h = __hmax2(__floats2half2_rn(ao[mt][0], ao[mt][1]), z2); A0[mt][np][2] = *(uint32_t*)&h;
                    h = __hmax2(__floats2half2_rn(ao[mt][2], ao[mt][3]), z2); A0[mt][np][3] = *(uint32_t*)&h;
                }
            }
        }

        // ---- mainloop (pr currently holds pos rows) ----
        run_layer<8, false>(A0, A1, sb + OFF_W1,             F + FB1, F, pr, offs, nlsh, lane);        // h1
        run_layer<8, true >(A1, A0, sb + OFF_W1 + GW_W2 * 2, F + FB2, F + FW2B, pr, offs, nlsh, lane); // h2 (+pos)
        run_layer<8, false>(A0, A1, sb + OFF_W1 + GW_W3 * 2, F + FB3, F, pr, offs, nlsh, lane);        // h3

        // ---- density head from h3 (A1) ----
        {
            const float bdv = F[FBD];
#pragma unroll
            for (int mt = 0; mt < 2; mt++) {
                float d0 = 0.f, d1 = 0.f;
#pragma unroll
                for (int kt = 0; kt < 8; kt++) {
                    int k0 = kt * 16 + cbase;
                    float2 wlo = *(const float2*)&F[FWD + k0];
                    float2 whi = *(const float2*)&F[FWD + k0 + 8];
                    float2 f0 = __half22float2(*(__half2*)&A1[mt][kt][0]);
                    float2 f1 = __half22float2(*(__half2*)&A1[mt][kt][1]);
                    float2 f2 = __half22float2(*(__half2*)&A1[mt][kt][2]);
                    float2 f3 = __half22float2(*(__half2*)&A1[mt][kt][3]);
                    d0 += f0.x * wlo.x + f0.y * wlo.y + f2.x * whi.x + f2.y * whi.y;
                    d1 += f1.x * wlo.x + f1.y * wlo.y + f3.x * whi.x + f3.y * whi.y;
                }
                d0 += __shfl_xor_sync(0xffffffffu, d0, 1); d0 += __shfl_xor_sync(0xffffffffu, d0, 2);
                d1 += __shfl_xor_sync(0xffffffffu, d1, 1); d1 += __shfl_xor_sync(0xffffffffu, d1, 2);
                if ((lane & 3) == 0) {
                    int Ra = s0 + w * 32 + mt * 16 + q;
                    out[3 * S_TOTAL + Ra]     = fmaxf(d0 + bdv, 0.f);
                    out[3 * S_TOTAL + Ra + 8] = fmaxf(d1 + bdv, 0.f);
                }
            }
        }

        // ---- reload pr with view rows; features + r-layer ----
#pragma unroll
        for (int mt = 0; mt < 2; mt++)
#pragma unroll
            for (int hf = 0; hf < 2; hf++) {
                int r = w * 32 + mt * 16 + hf * 8 + q;
                pr[mt][hf][0] = X[r * 6 + 3]; pr[mt][hf][1] = X[r * 6 + 4]; pr[mt][hf][2] = X[r * 6 + 5];
            }
        run_layer<8, false>(A1, A0, sb + OFF_W1 + GW_WF * 2, F + FBF, F, pr, offs, nlsh, lane);        // features
        run_layer<4, true >(A0, A1, sb + OFF_W1 + GW_WR * 2, F + FBR, F + FWRB, pr, offs, nlsh, lane); // r (+view)

        // ---- rgb head from r (A1, k-tiles 0..3) ----
        {
#pragma unroll
            for (int mt = 0; mt < 2; mt++) {
                float s[2][3] = {{0.f,0.f,0.f},{0.f,0.f,0.f}};
#pragma unroll
                for (int kt = 0; kt < 4; kt++) {
                    int k0 = kt * 16 + cbase, k8 = k0 + 8;
                    float2 f0 = __half22float2(*(__half2*)&A1[mt][kt][0]);
                    float2 f1 = __half22float2(*(__half2*)&A1[mt][kt][1]);
                    float2 f2 = __half22float2(*(__half2*)&A1[mt][kt][2]);
                    float2 f3 = __half22float2(*(__half2*)&A1[mt][kt][3]);
#pragma unroll
                    for (int c = 0; c < 3; c++) {
                        float w00 = F[FWO + k0 * 3 + c],       w01 = F[FWO + (k0 + 1) * 3 + c];
                        float w08 = F[FWO + k8 * 3 + c],       w09 = F[FWO + (k8 + 1) * 3 + c];
                        s[0][c] += f0.x * w00 + f0.y * w01 + f2.x * w08 + f2.y * w09;
                        s[1][c] += f1.x * w00 + f1.y * w01 + f3.x * w08 + f3.y * w09;
                    }
                }
#pragma unroll
                for (int hf = 0; hf < 2; hf++)
#pragma unroll
                    for (int c = 0; c < 3; c++) {
                        s[hf][c] += __shfl_xor_sync(0xffffffffu, s[hf][c], 1);
                        s[hf][c] += __shfl_xor_sync(0xffffffffu, s[hf][c], 2);
                    }
                if ((lane & 3) == 0) {
                    int Ra = s0 + w * 32 + mt * 16 + q;
#pragma unroll
                    for (int hf = 0; hf < 2; hf++) {
                        size_t o = (size_t)(Ra + hf * 8) * 3;
                        out[o + 0] = 1.f / (1.f + expf(-(s[hf][0] + F[FBO])));
                        out[o + 1] = 1.f / (1.f + expf(-(s[hf][1] + F[FBO + 1])));
                        out[o + 2] = 1.f / (1.f + expf(-(s[hf][2] + F[FBO + 2])));
                    }
                }
            }
        }
    }
}

extern "C" void kernel_launch(void* const* d_in, const int* in_sizes, int n_in,
                              void* d_out, int out_size) {
    (void)in_sizes; (void)n_in; (void)out_size;
    const float* x  = (const float*)d_in[0];
    const float* w0 = (const float*)d_in[1];  const float* b0 = (const float*)d_in[2];
    const float* w1 = (const float*)d_in[3];  const float* b1 = (const float*)d_in[4];
    const float* w2 = (const float*)d_in[5];  const float* b2 = (const float*)d_in[6];
    const float* w3 = (const float*)d_in[7];  const float* b3 = (const float*)d_in[8];
    const float* wd = (const float*)d_in[9];  const float* bd = (const float*)d_in[10];
    const float* wf = (const float*)d_in[11]; const float* bf = (const float*)d_in[12];
    const float* wr = (const float*)d_in[13]; const float* br = (const float*)d_in[14];
    const float* wo = (const float*)d_in[15]; const float* bo = (const float*)d_in[16];
    float* out = (float*)d_out;

    prep_weights<<<320, 256>>>(w1, w2, w3, wf, wr, w0, b0);

    cudaFuncSetAttribute(nerf_hmma_kernel,
                         cudaFuncAttributeMaxDynamicSharedMemorySize, SMEM_TOTAL);
    nerf_hmma_kernel<<<GRIDX, NT, SMEM_TOTAL>>>(
        x, b1, b2, b3, bd, bf, br, bo, w2, wr, wd, wo, out);
}